// round 1
// baseline (speedup 1.0000x reference)
#include <cuda_runtime.h>
#include <math.h>

// ---------------- problem constants ----------------
#define NG    128              // graphs
#define NPG   256              // nodes per graph
#define DF    128              // feature dim
#define KBINS 16
#define NSLOT (2*NG)           // 256 graph-instances (2 views)
#define SMS   264              // smem row stride (floats) for k-major tiles

// constants
#define BIN_STEP 0.2f          // 3/15
#define INV_SIG  (16.0f/3.0f)  // 1/sigma, sigma = 3/16
#define INV_TEMP 2.0f          // 1/0.5
#define LAMBDA   0.1f

// ---------------- device scratch (no allocs allowed) ----------------
__device__ float g_HT[(size_t)NSLOT * DF * NPG];     // [slot][k][node]  33.5MB
__device__ float g_D [(size_t)NSLOT * NPG * NPG];    // [slot][i][j]     67MB (3 of 4 macro quadrants written)
__device__ float g_sumD[NSLOT];
__device__ float g_hist[NSLOT * KBINS];
__device__ float g_rowloss[NSLOT];
__device__ float g_znT[DF * NSLOT];                  // [k][row] normalized z, transposed

// ---------------- f32x2 packed-FMA helpers ----------------
static __device__ __forceinline__ unsigned long long pk2(float lo, float hi) {
    unsigned long long r;
    asm("mov.b64 %0, {%1, %2};" : "=l"(r)
        : "r"(__float_as_uint(lo)), "r"(__float_as_uint(hi)));
    return r;
}
static __device__ __forceinline__ unsigned long long ffma2(
        unsigned long long a, unsigned long long b, unsigned long long c) {
    unsigned long long r;
    asm("fma.rn.f32x2 %0, %1, %2, %3;" : "=l"(r) : "l"(a), "l"(b), "l"(c));
    return r;
}
static __device__ __forceinline__ void up2(unsigned long long v, float& lo, float& hi) {
    unsigned ulo, uhi;
    asm("mov.b64 {%0, %1}, %2;" : "=r"(ulo), "=r"(uhi) : "l"(v));
    lo = __uint_as_float(ulo);
    hi = __uint_as_float(uhi);
}

// ---------------- kernel 1: global transpose H -> HT (k-major per graph) ----------------
__global__ __launch_bounds__(256) void k_transpose(const float* __restrict__ H1,
                                                   const float* __restrict__ H2) {
    int s = blockIdx.x;                 // 0..255
    int g = s & (NG - 1);
    const float* H = (s < NG ? H1 : H2) + (size_t)g * NPG * DF;
    float* out = g_HT + (size_t)s * DF * NPG;

    __shared__ float tile[32][33];
    int tx = threadIdx.x & 31;
    int tw = threadIdx.x >> 5;          // 0..7

    for (int t = 0; t < 32; t++) {      // 8 node-tiles x 4 k-tiles
        int tr = t >> 2;                // node tile
        int tc = t & 3;                 // k tile
        #pragma unroll
        for (int j = 0; j < 4; j++) {
            int y = tw + 8 * j;
            tile[y][tx] = H[(size_t)(tr * 32 + y) * DF + tc * 32 + tx];
        }
        __syncthreads();
        #pragma unroll
        for (int j = 0; j < 4; j++) {
            int y = tw + 8 * j;
            out[(size_t)(tc * 32 + y) * NPG + tr * 32 + tx] = tile[tx][y];
        }
        __syncthreads();
    }
}

// ---------------- kernel 2: normalize z rows, write transposed ----------------
__global__ __launch_bounds__(256) void k_znorm(const float* __restrict__ z1,
                                               const float* __restrict__ z2) {
    int t = threadIdx.x;                // row 0..255
    const float* zr = (t < NG) ? (z1 + (size_t)t * DF) : (z2 + (size_t)(t - NG) * DF);
    float ss = 0.f;
    for (int k = 0; k < DF; k++) { float v = zr[k]; ss += v * v; }
    float inv = 1.0f / (sqrtf(ss) + 1e-8f);
    for (int k = 0; k < DF; k++) g_znT[k * NSLOT + t] = zr[k] * inv;
}

// ---------------- kernel 3: pairwise distances (f32x2 GEMM) ----------------
// one block per graph-instance; computes macro quadrants (0,0),(0,1),(1,1)
__global__ __launch_bounds__(256, 1) void k_pairdist() {
    extern __shared__ float sm[];            // HsT[128][264]
    __shared__ float sq[NPG];
    __shared__ float rsum[8];

    int s = blockIdx.x;
    int tid = threadIdx.x;
    const float* HT = g_HT + (size_t)s * DF * NPG;
    float* Dout = g_D + (size_t)s * NPG * NPG;

    // load k-major tile: coalesced global float4, conflict-free smem stores
    const float4* src = (const float4*)HT;
    for (int i = tid; i < DF * NPG / 4; i += 256) {
        int k = i >> 6, c4 = i & 63;
        *(float4*)(sm + k * SMS + c4 * 4) = src[i];
    }
    __syncthreads();

    // squared norms per node (conflict-free: consecutive lanes -> consecutive banks)
    {
        float ssq = 0.f;
        for (int k = 0; k < DF; k++) { float v = sm[k * SMS + tid]; ssq += v * v; }
        sq[tid] = ssq;
    }
    __syncthreads();

    int tx = tid & 15, ty = tid >> 4;
    float tsum = 0.f;

    #pragma unroll 1
    for (int m = 0; m < 3; m++) {
        int rb = (m == 2) ? 1 : 0;
        int cb = (m >= 1) ? 1 : 0;
        float w = (m == 1) ? 2.0f : 1.0f;
        int row0 = rb * 128 + ty * 8;
        int col0 = cb * 128 + tx * 8;

        unsigned long long acc[8][4];
        #pragma unroll
        for (int r = 0; r < 8; r++)
            #pragma unroll
            for (int j = 0; j < 4; j++) acc[r][j] = 0ULL;   // (0.f,0.f)

        #pragma unroll 1
        for (int k = 0; k < DF; k++) {
            const float* rp = sm + k * SMS;
            float4 a0 = *(const float4*)(rp + row0);
            float4 a1 = *(const float4*)(rp + row0 + 4);
            float4 b0 = *(const float4*)(rp + col0);
            float4 b1 = *(const float4*)(rp + col0 + 4);
            unsigned long long pb0 = pk2(b0.x, b0.y);
            unsigned long long pb1 = pk2(b0.z, b0.w);
            unsigned long long pb2 = pk2(b1.x, b1.y);
            unsigned long long pb3 = pk2(b1.z, b1.w);
            float av[8] = {a0.x, a0.y, a0.z, a0.w, a1.x, a1.y, a1.z, a1.w};
            #pragma unroll
            for (int r = 0; r < 8; r++) {
                unsigned long long pa = pk2(av[r], av[r]);
                acc[r][0] = ffma2(pa, pb0, acc[r][0]);
                acc[r][1] = ffma2(pa, pb1, acc[r][1]);
                acc[r][2] = ffma2(pa, pb2, acc[r][2]);
                acc[r][3] = ffma2(pa, pb3, acc[r][3]);
            }
        }

        float sqj[8];
        #pragma unroll
        for (int c = 0; c < 8; c++) sqj[c] = sq[col0 + c];

        #pragma unroll
        for (int r = 0; r < 8; r++) {
            int gi = row0 + r;
            float sqi = sq[gi];
            float dots[8];
            up2(acc[r][0], dots[0], dots[1]);
            up2(acc[r][1], dots[2], dots[3]);
            up2(acc[r][2], dots[4], dots[5]);
            up2(acc[r][3], dots[6], dots[7]);
            float o[8];
            #pragma unroll
            for (int c = 0; c < 8; c++) {
                float d2 = sqi + sqj[c] - 2.0f * dots[c];
                float dd = sqrtf(fmaxf(d2, 0.0f) + 1e-12f);
                o[c] = dd;
                tsum += w * dd;
            }
            float4 v0 = {o[0], o[1], o[2], o[3]};
            float4 v1 = {o[4], o[5], o[6], o[7]};
            *(float4*)(Dout + (size_t)gi * NPG + col0)     = v0;
            *(float4*)(Dout + (size_t)gi * NPG + col0 + 4) = v1;
        }
    }

    // deterministic block reduction of tsum
    #pragma unroll
    for (int off = 16; off > 0; off >>= 1)
        tsum += __shfl_down_sync(0xffffffffu, tsum, off);
    if ((tid & 31) == 0) rsum[tid >> 5] = tsum;
    __syncthreads();
    if (tid == 0) {
        float tot = 0.f;
        #pragma unroll
        for (int wI = 0; wI < 8; wI++) tot += rsum[wI];
        g_sumD[s] = tot;
    }
}

// ---------------- kernel 4: soft histogram per graph-instance ----------------
__global__ __launch_bounds__(256) void k_hist() {
    int s = blockIdx.x;
    int tid = threadIdx.x;
    const float* Dp = g_D + (size_t)s * NPG * NPG;

    float mean = g_sumD[s] * (1.0f / (float)(NPG * NPG));
    float invs = (1.0f / (mean + 1e-8f)) * INV_SIG;   // Dn*INV_SIG in one mul

    float acc[KBINS];
    #pragma unroll
    for (int k = 0; k < KBINS; k++) acc[k] = 0.f;

    const int R0[3] = {0, 0, 128};
    const int C0[3] = {0, 128, 128};
    const float W[3] = {1.0f, 2.0f, 1.0f};

    #pragma unroll 1
    for (int m = 0; m < 3; m++) {
        float w = W[m];
        const float* base = Dp + (size_t)R0[m] * NPG + C0[m];
        for (int i = tid; i < 4096; i += 256) {        // 16384 floats / 4
            int rr = i >> 5, c4 = i & 31;
            float4 dv = *(const float4*)(base + (size_t)rr * NPG + c4 * 4);
            float dd[4] = {dv.x, dv.y, dv.z, dv.w};
            #pragma unroll
            for (int e = 0; e < 4; e++) {
                float us = dd[e] * invs;
                #pragma unroll
                for (int k = 0; k < KBINS; k++) {
                    float t = us - (float)k * (BIN_STEP * INV_SIG);
                    acc[k] += w * __expf(-0.5f * t * t);
                }
            }
        }
    }

    // deterministic reduce: warp shuffle, then fixed-order across 8 warps
    __shared__ float hsm[8][KBINS];
    __shared__ float fin[KBINS];
    #pragma unroll
    for (int k = 0; k < KBINS; k++) {
        float v = acc[k];
        #pragma unroll
        for (int off = 16; off > 0; off >>= 1)
            v += __shfl_down_sync(0xffffffffu, v, off);
        if ((tid & 31) == 0) hsm[tid >> 5, 0 ? 0 : 0][k] = v;   // placeholder avoided below
    }
    // NOTE: rewrite the store cleanly (comma trick above is identity)
    __syncthreads();
    // redo stores safely (cheap): recompute warp sums into hsm
    #pragma unroll
    for (int k = 0; k < KBINS; k++) {
        float v = acc[k];
        #pragma unroll
        for (int off = 16; off > 0; off >>= 1)
            v += __shfl_down_sync(0xffffffffu, v, off);
        if ((tid & 31) == 0) hsm[tid >> 5][k] = v;
    }
    __syncthreads();
    if (tid < KBINS) {
        float t = 0.f;
        #pragma unroll
        for (int wI = 0; wI < 8; wI++) t += hsm[wI][tid];
        fin[tid] = t;
    }
    __syncthreads();
    if (tid < KBINS) {
        float tot = 0.f;
        #pragma unroll
        for (int j = 0; j < KBINS; j++) tot += fin[j];   // same order on all lanes
        g_hist[s * KBINS + tid] = fin[tid] / (tot + 1e-8f);
    }
}

// ---------------- kernel 5: NT-Xent row losses ----------------
__global__ __launch_bounds__(256) void k_ntxent() {
    extern __shared__ float zs[];            // zsT[128][264]
    __shared__ float simb[4][260];
    __shared__ float red[4][64];

    int tid = threadIdx.x;
    int r0 = blockIdx.x * 4;

    const float4* src = (const float4*)g_znT;
    for (int i = tid; i < DF * NSLOT / 4; i += 256) {
        int k = i >> 6, c4 = i & 63;
        *(float4*)(zs + k * SMS + c4 * 4) = src[i];
    }
    __syncthreads();

    int lr = tid >> 6;        // local row 0..3
    int cq = tid & 63;        // column quad
    int row = r0 + lr;
    int c0 = cq * 4;

    float a0 = 0.f, a1 = 0.f, a2 = 0.f, a3 = 0.f;
    for (int k = 0; k < DF; k++) {
        const float* rp = zs + k * SMS;
        float a = rp[row];
        float4 b = *(const float4*)(rp + c0);
        a0 += a * b.x; a1 += a * b.y; a2 += a * b.z; a3 += a * b.w;
    }
    float s0 = a0 * INV_TEMP, s1 = a1 * INV_TEMP, s2 = a2 * INV_TEMP, s3 = a3 * INV_TEMP;
    if (c0 + 0 == row) s0 = -1e9f;
    if (c0 + 1 == row) s1 = -1e9f;
    if (c0 + 2 == row) s2 = -1e9f;
    if (c0 + 3 == row) s3 = -1e9f;
    float4 sv = {s0, s1, s2, s3};
    *(float4*)&simb[lr][c0] = sv;
    __syncthreads();

    // row max (tree over 64 threads per row, uniform syncs)
    float lm = fmaxf(fmaxf(s0, s1), fmaxf(s2, s3));
    red[lr][cq] = lm;
    __syncthreads();
    for (int st = 32; st > 0; st >>= 1) {
        if (cq < st) red[lr][cq] = fmaxf(red[lr][cq], red[lr][cq + st]);
        __syncthreads();
    }
    float rmax = red[lr][0];
    __syncthreads();

    float se = __expf(s0 - rmax) + __expf(s1 - rmax) + __expf(s2 - rmax) + __expf(s3 - rmax);
    red[lr][cq] = se;
    __syncthreads();
    for (int st = 32; st > 0; st >>= 1) {
        if (cq < st) red[lr][cq] += red[lr][cq + st];
        __syncthreads();
    }
    if (cq == 0) {
        float lse = rmax + logf(red[lr][0]);
        int label = (row < NG) ? row + NG : row - NG;
        g_rowloss[row] = lse - simb[lr][label];
    }
}

// ---------------- kernel 6: final scalar ----------------
__global__ __launch_bounds__(256) void k_final(float* __restrict__ out) {
    __shared__ float red[256];
    __shared__ float tsave;
    int t = threadIdx.x;

    float v = 0.f;
    if (t < NG) {
        float m = 0.f;
        #pragma unroll
        for (int k = 0; k < KBINS; k++) {
            float d = g_hist[t * KBINS + k] - g_hist[(t + NG) * KBINS + k];
            m += d * d;
        }
        v = m * (1.0f / KBINS);
    }
    red[t] = v;
    __syncthreads();
    for (int st = 128; st > 0; st >>= 1) {
        if (t < st) red[t] += red[t + st];
        __syncthreads();
    }
    if (t == 0) tsave = red[0];
    __syncthreads();

    red[t] = g_rowloss[t];
    __syncthreads();
    for (int st = 128; st > 0; st >>= 1) {
        if (t < st) red[t] += red[t + st];
        __syncthreads();
    }
    if (t == 0) {
        float topo = tsave * (1.0f / NG);
        float ntx  = red[0] * (1.0f / NSLOT);
        out[0] = LAMBDA * (topo + ntx);
    }
}

// ---------------- launcher ----------------
extern "C" void kernel_launch(void* const* d_in, const int* in_sizes, int n_in,
                              void* d_out, int out_size) {
    const float* H1 = (const float*)d_in[0];
    const float* H2 = (const float*)d_in[2];
    const float* z1 = (const float*)d_in[4];
    const float* z2 = (const float*)d_in[5];
    float* out = (float*)d_out;

    const int dynsm = DF * SMS * sizeof(float);   // 135168
    cudaFuncSetAttribute(k_pairdist, cudaFuncAttributeMaxDynamicSharedMemorySize, dynsm);
    cudaFuncSetAttribute(k_ntxent,   cudaFuncAttributeMaxDynamicSharedMemorySize, dynsm);

    k_transpose<<<NSLOT, 256>>>(H1, H2);
    k_znorm<<<1, 256>>>(z1, z2);
    k_pairdist<<<NSLOT, 256, dynsm>>>();
    k_hist<<<NSLOT, 256>>>();
    k_ntxent<<<64, 256, dynsm>>>();
    k_final<<<1, 256>>>(out);
}

// round 2
// speedup vs baseline: 1.2524x; 1.2524x over previous
#include <cuda_runtime.h>
#include <math.h>

// ---------------- problem constants ----------------
#define NG    128              // graphs
#define NPG   256              // nodes per graph
#define DF    128              // feature dim
#define KBINS 16
#define NSLOT (2*NG)           // 256 graph-instances (2 views)
#define SMS   264              // smem row stride (floats) for k-major tiles

#define INV_TEMP 2.0f
#define LAMBDA   0.1f

// Gaussian-histogram constants (bin units: centers at integers, Delta=0.2 in Dn units)
// sigma' = (3/16)/0.2 = 0.9375 ; a = -0.5/sigma'^2 = -0.56888889
// A = a * log2(e)
#define GA (-0.82073318f)

// ---------------- device scratch ----------------
__device__ float g_HT[(size_t)NSLOT * DF * NPG];     // [slot][k][node]
__device__ float g_D [(size_t)NSLOT * NPG * NPG];    // [slot][i][j] (3 of 4 quadrants valid)
__device__ float g_sumD[NSLOT];
__device__ float g_hpart[NSLOT * 4 * KBINS];         // partial (unnormalized) hists
__device__ float g_rowloss[NSLOT];
__device__ float g_znT[DF * NSLOT];

// ---------------- f32x2 helpers ----------------
static __device__ __forceinline__ unsigned long long pk2(float lo, float hi) {
    unsigned long long r;
    asm("mov.b64 %0, {%1, %2};" : "=l"(r)
        : "r"(__float_as_uint(lo)), "r"(__float_as_uint(hi)));
    return r;
}
static __device__ __forceinline__ unsigned long long ffma2(
        unsigned long long a, unsigned long long b, unsigned long long c) {
    unsigned long long r;
    asm("fma.rn.f32x2 %0, %1, %2, %3;" : "=l"(r) : "l"(a), "l"(b), "l"(c));
    return r;
}
static __device__ __forceinline__ unsigned long long mul2(
        unsigned long long a, unsigned long long b) {
    unsigned long long r;
    asm("mul.rn.f32x2 %0, %1, %2;" : "=l"(r) : "l"(a), "l"(b));
    return r;
}
static __device__ __forceinline__ void up2(unsigned long long v, float& lo, float& hi) {
    unsigned ulo, uhi;
    asm("mov.b64 {%0, %1}, %2;" : "=r"(ulo), "=r"(uhi) : "l"(v));
    lo = __uint_as_float(ulo);
    hi = __uint_as_float(uhi);
}
static __device__ __forceinline__ float ex2f(float x) {
    float r;
    asm("ex2.approx.f32 %0, %1;" : "=f"(r) : "f"(x));
    return r;
}

// ---------------- kernel 1: transpose H -> HT (k-major per graph) + znorm ----------------
__global__ __launch_bounds__(256) void k_transpose(const float* __restrict__ H1,
                                                   const float* __restrict__ H2,
                                                   const float* __restrict__ z1,
                                                   const float* __restrict__ z2) {
    int s = blockIdx.x;                 // 0..255
    int g = s & (NG - 1);
    const float* H = (s < NG ? H1 : H2) + (size_t)g * NPG * DF;
    float* out = g_HT + (size_t)s * DF * NPG;

    __shared__ float tile[32][33];
    int tx = threadIdx.x & 31;
    int tw = threadIdx.x >> 5;          // 0..7

    for (int t = 0; t < 32; t++) {      // 8 node-tiles x 4 k-tiles
        int tr = t >> 2;
        int tc = t & 3;
        #pragma unroll
        for (int j = 0; j < 4; j++) {
            int y = tw + 8 * j;
            tile[y][tx] = H[(size_t)(tr * 32 + y) * DF + tc * 32 + tx];
        }
        __syncthreads();
        #pragma unroll
        for (int j = 0; j < 4; j++) {
            int y = tw + 8 * j;
            out[(size_t)(tc * 32 + y) * NPG + tr * 32 + tx] = tile[tx][y];
        }
        __syncthreads();
    }

    // block 0 additionally normalizes z rows into transposed layout
    if (s == 0) {
        int t = threadIdx.x;            // row 0..255
        const float* zr = (t < NG) ? (z1 + (size_t)t * DF) : (z2 + (size_t)(t - NG) * DF);
        float ss = 0.f;
        for (int k = 0; k < DF; k++) { float v = zr[k]; ss += v * v; }
        float inv = 1.0f / (sqrtf(ss) + 1e-8f);
        for (int k = 0; k < DF; k++) g_znT[k * NSLOT + t] = zr[k] * inv;
    }
}

// ---------------- kernel 2: pairwise distances (f32x2 GEMM) ----------------
__global__ __launch_bounds__(256, 1) void k_pairdist() {
    extern __shared__ float sm[];            // HsT[128][264]
    __shared__ float sq[NPG];
    __shared__ float rsum[8];

    int s = blockIdx.x;
    int tid = threadIdx.x;
    const float* HT = g_HT + (size_t)s * DF * NPG;
    float* Dout = g_D + (size_t)s * NPG * NPG;

    const float4* src = (const float4*)HT;
    for (int i = tid; i < DF * NPG / 4; i += 256) {
        int k = i >> 6, c4 = i & 63;
        *(float4*)(sm + k * SMS + c4 * 4) = src[i];
    }
    __syncthreads();

    {
        float ssq = 0.f;
        for (int k = 0; k < DF; k++) { float v = sm[k * SMS + tid]; ssq += v * v; }
        sq[tid] = ssq;
    }
    __syncthreads();

    int tx = tid & 15, ty = tid >> 4;
    float tsum = 0.f;

    #pragma unroll 1
    for (int m = 0; m < 3; m++) {
        int rb = (m == 2) ? 1 : 0;
        int cb = (m >= 1) ? 1 : 0;
        float w = (m == 1) ? 2.0f : 1.0f;
        int row0 = rb * 128 + ty * 8;
        int col0 = cb * 128 + tx * 8;

        unsigned long long acc[8][4];
        #pragma unroll
        for (int r = 0; r < 8; r++)
            #pragma unroll
            for (int j = 0; j < 4; j++) acc[r][j] = 0ULL;

        #pragma unroll 1
        for (int k = 0; k < DF; k++) {
            const float* rp = sm + k * SMS;
            float4 a0 = *(const float4*)(rp + row0);
            float4 a1 = *(const float4*)(rp + row0 + 4);
            // b loaded directly as packed u64 pairs (memory layout == pk2 layout)
            ulonglong2 bq0 = *(const ulonglong2*)(rp + col0);
            ulonglong2 bq1 = *(const ulonglong2*)(rp + col0 + 4);
            unsigned long long pb0 = bq0.x, pb1 = bq0.y, pb2 = bq1.x, pb3 = bq1.y;
            float av[8] = {a0.x, a0.y, a0.z, a0.w, a1.x, a1.y, a1.z, a1.w};
            #pragma unroll
            for (int r = 0; r < 8; r++) {
                unsigned long long pa = pk2(av[r], av[r]);
                acc[r][0] = ffma2(pa, pb0, acc[r][0]);
                acc[r][1] = ffma2(pa, pb1, acc[r][1]);
                acc[r][2] = ffma2(pa, pb2, acc[r][2]);
                acc[r][3] = ffma2(pa, pb3, acc[r][3]);
            }
        }

        float sqj[8];
        #pragma unroll
        for (int c = 0; c < 8; c++) sqj[c] = sq[col0 + c];

        #pragma unroll
        for (int r = 0; r < 8; r++) {
            int gi = row0 + r;
            float sqi = sq[gi];
            float dots[8];
            up2(acc[r][0], dots[0], dots[1]);
            up2(acc[r][1], dots[2], dots[3]);
            up2(acc[r][2], dots[4], dots[5]);
            up2(acc[r][3], dots[6], dots[7]);
            float o[8];
            #pragma unroll
            for (int c = 0; c < 8; c++) {
                float d2 = sqi + sqj[c] - 2.0f * dots[c];
                float dd = sqrtf(fmaxf(d2, 0.0f) + 1e-12f);
                o[c] = dd;
                tsum += w * dd;
            }
            float4 v0 = {o[0], o[1], o[2], o[3]};
            float4 v1 = {o[4], o[5], o[6], o[7]};
            *(float4*)(Dout + (size_t)gi * NPG + col0)     = v0;
            *(float4*)(Dout + (size_t)gi * NPG + col0 + 4) = v1;
        }
    }

    #pragma unroll
    for (int off = 16; off > 0; off >>= 1)
        tsum += __shfl_down_sync(0xffffffffu, tsum, off);
    if ((tid & 31) == 0) rsum[tid >> 5] = tsum;
    __syncthreads();
    if (tid == 0) {
        float tot = 0.f;
        #pragma unroll
        for (int wI = 0; wI < 8; wI++) tot += rsum[wI];
        g_sumD[s] = tot;
    }
}

// ---------------- kernel 3: soft histogram (recurrence + f32x2) ----------------
// grid = NSLOT*4 ; block b handles slot b>>2, chunk b&3 (3072 float4 loads)
__global__ __launch_bounds__(256) void k_hist() {
    int s    = blockIdx.x >> 2;
    int part = blockIdx.x & 3;
    int tid  = threadIdx.x;
    const float* Dp = g_D + (size_t)s * NPG * NPG;

    float mean = g_sumD[s] * (1.0f / 65536.0f);
    float sbin = 5.0f / (mean + 1e-8f);          // p = d * sbin   (bin units)

    float su_s = ex2f(2.0f * GA);                // exp(2a) as multiplier
    unsigned long long su2 = pk2(su_s, su_s);

    unsigned long long acc[KBINS];
    #pragma unroll
    for (int k = 0; k < KBINS; k++) acc[k] = 0ULL;

    int i0 = part * 3072 + tid;                  // 12 iterations of stride 256
    #pragma unroll 1
    for (int it = 0; it < 12; it++, i0 += 256) {
        int q  = i0 >> 12;                       // quadrant 0,1,2
        int lq = i0 & 4095;
        int rr = lq >> 5, c4 = lq & 31;
        int roff = (q >> 1) << 7;
        int coff = q ? 128 : 0;
        const float4 dv = *(const float4*)(Dp + (size_t)(roff + rr) * NPG + coff + c4 * 4);
        float wq = (q == 1) ? 2.0f : 1.0f;
        unsigned long long wq2 = pk2(wq, wq);

        float dd[4] = {dv.x, dv.y, dv.z, dv.w};
        #pragma unroll
        for (int pp = 0; pp < 2; pp++) {
            float d0 = dd[pp * 2], d1 = dd[pp * 2 + 1];
            float p0 = d0 * sbin, p1 = d1 * sbin;
            float t0 = p0 - 7.0f, t1 = p1 - 7.0f;
            float w70 = ex2f((GA * t0) * t0);
            float w71 = ex2f((GA * t1) * t1);
            float ru0 = ex2f(fmaf(-2.0f * GA, p0, 15.0f * GA));
            float ru1 = ex2f(fmaf(-2.0f * GA, p1, 15.0f * GA));
            float rd0 = ex2f(fmaf( 2.0f * GA, p0, -13.0f * GA));
            float rd1 = ex2f(fmaf( 2.0f * GA, p1, -13.0f * GA));
            unsigned long long w7 = pk2(w70, w71);
            unsigned long long ru = pk2(ru0, ru1);
            unsigned long long rd = pk2(rd0, rd1);

            acc[7] = ffma2(w7, wq2, acc[7]);
            unsigned long long wu = w7;
            #pragma unroll
            for (int k = 8; k < 16; k++) {
                wu = mul2(wu, ru);
                acc[k] = ffma2(wu, wq2, acc[k]);
                ru = mul2(ru, su2);
            }
            unsigned long long wd = w7;
            #pragma unroll
            for (int k = 6; k >= 0; k--) {
                wd = mul2(wd, rd);
                acc[k] = ffma2(wd, wq2, acc[k]);
                rd = mul2(rd, su2);
            }
        }
    }

    // deterministic block reduction -> partial hist
    __shared__ float hsm[8][KBINS];
    #pragma unroll
    for (int k = 0; k < KBINS; k++) {
        float lo, hi;
        up2(acc[k], lo, hi);
        float v = lo + hi;
        #pragma unroll
        for (int off = 16; off > 0; off >>= 1)
            v += __shfl_down_sync(0xffffffffu, v, off);
        if ((tid & 31) == 0) hsm[tid >> 5][k] = v;
    }
    __syncthreads();
    if (tid < KBINS) {
        float t = 0.f;
        #pragma unroll
        for (int wI = 0; wI < 8; wI++) t += hsm[wI][tid];
        g_hpart[(s * 4 + part) * KBINS + tid] = t;
    }
}

// ---------------- kernel 4: NT-Xent row losses ----------------
__global__ __launch_bounds__(256) void k_ntxent() {
    extern __shared__ float zs[];            // zsT[128][264]
    __shared__ float simb[4][260];
    __shared__ float red[4][64];

    int tid = threadIdx.x;
    int r0 = blockIdx.x * 4;

    const float4* src = (const float4*)g_znT;
    for (int i = tid; i < DF * NSLOT / 4; i += 256) {
        int k = i >> 6, c4 = i & 63;
        *(float4*)(zs + k * SMS + c4 * 4) = src[i];
    }
    __syncthreads();

    int lr = tid >> 6;
    int cq = tid & 63;
    int row = r0 + lr;
    int c0 = cq * 4;

    float a0 = 0.f, a1 = 0.f, a2 = 0.f, a3 = 0.f;
    for (int k = 0; k < DF; k++) {
        const float* rp = zs + k * SMS;
        float a = rp[row];
        float4 b = *(const float4*)(rp + c0);
        a0 += a * b.x; a1 += a * b.y; a2 += a * b.z; a3 += a * b.w;
    }
    float s0 = a0 * INV_TEMP, s1 = a1 * INV_TEMP, s2 = a2 * INV_TEMP, s3 = a3 * INV_TEMP;
    if (c0 + 0 == row) s0 = -1e9f;
    if (c0 + 1 == row) s1 = -1e9f;
    if (c0 + 2 == row) s2 = -1e9f;
    if (c0 + 3 == row) s3 = -1e9f;
    float4 sv = {s0, s1, s2, s3};
    *(float4*)&simb[lr][c0] = sv;
    __syncthreads();

    float lm = fmaxf(fmaxf(s0, s1), fmaxf(s2, s3));
    red[lr][cq] = lm;
    __syncthreads();
    for (int st = 32; st > 0; st >>= 1) {
        if (cq < st) red[lr][cq] = fmaxf(red[lr][cq], red[lr][cq + st]);
        __syncthreads();
    }
    float rmax = red[lr][0];
    __syncthreads();

    float se = __expf(s0 - rmax) + __expf(s1 - rmax) + __expf(s2 - rmax) + __expf(s3 - rmax);
    red[lr][cq] = se;
    __syncthreads();
    for (int st = 32; st > 0; st >>= 1) {
        if (cq < st) red[lr][cq] += red[lr][cq + st];
        __syncthreads();
    }
    if (cq == 0) {
        float lse = rmax + logf(red[lr][0]);
        int label = (row < NG) ? row + NG : row - NG;
        g_rowloss[row] = lse - simb[lr][label];
    }
}

// ---------------- kernel 5: merge hists + final scalar ----------------
__global__ __launch_bounds__(256) void k_final(float* __restrict__ out) {
    __shared__ float red[256];
    __shared__ float tsave;
    int t = threadIdx.x;

    float v = 0.f;
    if (t < NG) {
        float h1[KBINS], h2[KBINS];
        float sA = 0.f, sB = 0.f;
        #pragma unroll
        for (int k = 0; k < KBINS; k++) {
            float a = 0.f, b = 0.f;
            #pragma unroll
            for (int p = 0; p < 4; p++) {
                a += g_hpart[(t * 4 + p) * KBINS + k];
                b += g_hpart[((t + NG) * 4 + p) * KBINS + k];
            }
            h1[k] = a; h2[k] = b; sA += a; sB += b;
        }
        float iA = 1.f / (sA + 1e-8f), iB = 1.f / (sB + 1e-8f);
        float m = 0.f;
        #pragma unroll
        for (int k = 0; k < KBINS; k++) {
            float d = h1[k] * iA - h2[k] * iB;
            m += d * d;
        }
        v = m * (1.0f / KBINS);
    }
    red[t] = v;
    __syncthreads();
    for (int st = 128; st > 0; st >>= 1) {
        if (t < st) red[t] += red[t + st];
        __syncthreads();
    }
    if (t == 0) tsave = red[0];
    __syncthreads();

    red[t] = g_rowloss[t];
    __syncthreads();
    for (int st = 128; st > 0; st >>= 1) {
        if (t < st) red[t] += red[t + st];
        __syncthreads();
    }
    if (t == 0) {
        float topo = tsave * (1.0f / NG);
        float ntx  = red[0] * (1.0f / NSLOT);
        out[0] = LAMBDA * (topo + ntx);
    }
}

// ---------------- launcher ----------------
extern "C" void kernel_launch(void* const* d_in, const int* in_sizes, int n_in,
                              void* d_out, int out_size) {
    const float* H1 = (const float*)d_in[0];
    const float* H2 = (const float*)d_in[2];
    const float* z1 = (const float*)d_in[4];
    const float* z2 = (const float*)d_in[5];
    float* out = (float*)d_out;

    const int dynsm = DF * SMS * sizeof(float);   // 135168
    cudaFuncSetAttribute(k_pairdist, cudaFuncAttributeMaxDynamicSharedMemorySize, dynsm);
    cudaFuncSetAttribute(k_ntxent,   cudaFuncAttributeMaxDynamicSharedMemorySize, dynsm);

    k_transpose<<<NSLOT, 256>>>(H1, H2, z1, z2);
    k_pairdist<<<NSLOT, 256, dynsm>>>();
    k_hist<<<NSLOT * 4, 256>>>();
    k_ntxent<<<64, 256, dynsm>>>();
    k_final<<<1, 256>>>(out);
}